// round 14
// baseline (speedup 1.0000x reference)
#include <cuda_runtime.h>
#include <cuda_fp16.h>

#define B_DIM 32
#define N_IN 1000000
#define N_OUT 500000
#define TILE_O 128
#define SOUT_STRIDE 132   // floats per b-row: = 4 mod 32, float4-aligned
#define NTILES ((N_OUT + TILE_O - 1) / TILE_O)   // 3907
#define GATHER_BLOCKS (148 * 4)                  // persistent grid

// 64 MB transposed fp16 scratch: xt[i][b] -> one 64B line per input column i.
// Kept L2-resident: all other streams use evict-first hints.
__device__ __half g_xt[(size_t)N_IN * B_DIM];

// ---------------------------------------------------------------------------
// Kernel 1: transpose+convert x(32,1e6) fp32 -> xt(1e6,32) fp16. (unchanged)
// ---------------------------------------------------------------------------
__global__ void __launch_bounds__(256) transpose_kernel(const float* __restrict__ x) {
    __shared__ float tile[32][129];
    const int t    = threadIdx.x;
    const int col0 = blockIdx.x * 128;

    {
        const int row = t >> 5;
        const int c4  = col0 + 4 * (t & 31);
        if (c4 < N_IN) {
            #pragma unroll
            for (int r = 0; r < 32; r += 8) {
                float4 v = __ldcs(reinterpret_cast<const float4*>(
                    &x[(size_t)(row + r) * N_IN + c4]));
                tile[row + r][4 * (t & 31) + 0] = v.x;
                tile[row + r][4 * (t & 31) + 1] = v.y;
                tile[row + r][4 * (t & 31) + 2] = v.z;
                tile[row + r][4 * (t & 31) + 3] = v.w;
            }
        }
    }
    __syncthreads();

    #pragma unroll
    for (int m = 0; m < 2; m++) {
        const int e  = m * 256 + t;
        const int cc = e >> 2;
        const int q  = e & 3;
        if (col0 + cc < N_IN) {
            __half2 h0 = __floats2half2_rn(tile[8 * q + 0][cc], tile[8 * q + 1][cc]);
            __half2 h1 = __floats2half2_rn(tile[8 * q + 2][cc], tile[8 * q + 3][cc]);
            __half2 h2 = __floats2half2_rn(tile[8 * q + 4][cc], tile[8 * q + 5][cc]);
            __half2 h3 = __floats2half2_rn(tile[8 * q + 6][cc], tile[8 * q + 7][cc]);
            uint4 u;
            u.x = *reinterpret_cast<unsigned*>(&h0);
            u.y = *reinterpret_cast<unsigned*>(&h1);
            u.z = *reinterpret_cast<unsigned*>(&h2);
            u.w = *reinterpret_cast<unsigned*>(&h3);
            *reinterpret_cast<uint4*>(
                &g_xt[(size_t)(col0 + cc) * B_DIM + 8 * q]) = u;   // keep in L2
        }
    }
}

// ---------------------------------------------------------------------------
// Kernel 2: PERSISTENT double-buffered gather-reduce. 592 blocks loop over
// 3907 tiles of 128 outputs. Each steady-state phase mixes three streams:
//   gather LDG.128 (tile t) + idx/w staging LDG (tile t+grid) + out STG (t-grid)
// with ONE barrier per tile. s_pair and s_out both double-buffered.
// ---------------------------------------------------------------------------
__device__ __forceinline__ void stage_pairs(const int* __restrict__ idx,
                                            const float* __restrict__ w,
                                            int tile, int tid, int2* sp) {
    const int col0 = tile * TILE_O;
    #pragma unroll
    for (int m = 0; m < 2; m++) {
        const int e = m * 256 + tid;
        if (e < 3 * TILE_O) {
            const int gi = col0 * 3 + e;
            const bool v = (gi < 3 * N_OUT);
            sp[e] = make_int2(v ? __ldcs(&idx[gi]) : 0,
                              v ? __float_as_int(__ldcs(&w[gi])) : 0);
        }
    }
}

__device__ __forceinline__ void gather_phase(const int2* sp, float* so,
                                             int col0, int warp, int g, int s) {
    #pragma unroll
    for (int it = 0; it < 2; it++) {
        const int base = warp * 16 + it * 8;
        if (col0 + base < N_OUT) {
            const int ol = base + g;
            float acc[8] = {0, 0, 0, 0, 0, 0, 0, 0};
            #pragma unroll
            for (int k = 0; k < 3; k++) {
                const int2  p  = sp[ol * 3 + k];
                const float wk = __int_as_float(p.y);
                const uint4 v  = *reinterpret_cast<const uint4*>(
                    &g_xt[(size_t)p.x * B_DIM + 8 * s]);
                const float2 f0 = __half22float2(*reinterpret_cast<const __half2*>(&v.x));
                const float2 f1 = __half22float2(*reinterpret_cast<const __half2*>(&v.y));
                const float2 f2 = __half22float2(*reinterpret_cast<const __half2*>(&v.z));
                const float2 f3 = __half22float2(*reinterpret_cast<const __half2*>(&v.w));
                acc[0] = fmaf(wk, f0.x, acc[0]);
                acc[1] = fmaf(wk, f0.y, acc[1]);
                acc[2] = fmaf(wk, f1.x, acc[2]);
                acc[3] = fmaf(wk, f1.y, acc[3]);
                acc[4] = fmaf(wk, f2.x, acc[4]);
                acc[5] = fmaf(wk, f2.y, acc[5]);
                acc[6] = fmaf(wk, f3.x, acc[6]);
                acc[7] = fmaf(wk, f3.y, acc[7]);
            }
            const int colsw = ol ^ (8 * s);   // 16B-granular XOR swizzle
            #pragma unroll
            for (int i = 0; i < 8; i++) {
                so[(8 * s + i) * SOUT_STRIDE + colsw] = acc[i];
            }
        }
    }
}

__device__ __forceinline__ void write_phase(float* __restrict__ out,
                                            const float* so, int tile, int tid) {
    const int col0 = tile * TILE_O;
    #pragma unroll
    for (int m = 0; m < 4; m++) {
        const int f4 = m * 256 + tid;
        const int b  = f4 >> 5;
        const int c4 = (f4 & 31) * 4;
        const int oc = col0 + c4;
        if (oc < N_OUT) {
            const int cst = c4 ^ (8 * (b >> 3));
            float4 vv = *reinterpret_cast<const float4*>(
                &so[b * SOUT_STRIDE + cst]);
            __stcs(reinterpret_cast<float4*>(&out[(size_t)b * N_OUT + oc]), vv);
        }
    }
}

__global__ void __launch_bounds__(256, 4) gather_kernel(const float* __restrict__ w,
                                                        const int*   __restrict__ idx,
                                                        float*       __restrict__ out) {
    __shared__ int2  s_pair[2][3 * TILE_O];
    __shared__ float s_out[2][32 * SOUT_STRIDE];

    const int tid  = threadIdx.x;
    const int warp = tid >> 5;
    const int lane = tid & 31;
    const int g    = lane >> 2;
    const int s    = lane & 3;

    int t      = blockIdx.x;
    int cur    = 0;
    int prev_t = -1;

    if (t < NTILES) stage_pairs(idx, w, t, tid, s_pair[0]);
    __syncthreads();

    for (; t < NTILES; t += gridDim.x) {
        // Mixed-stream phase: gather(t) + stage(t+grid) + write(t-grid).
        gather_phase(s_pair[cur], s_out[cur], t * TILE_O, warp, g, s);
        const int nxt = t + gridDim.x;
        if (nxt < NTILES) stage_pairs(idx, w, nxt, tid, s_pair[cur ^ 1]);
        if (prev_t >= 0)  write_phase(out, s_out[cur ^ 1], prev_t, tid);
        __syncthreads();
        prev_t = t;
        cur ^= 1;
    }
    if (prev_t >= 0) write_phase(out, s_out[cur ^ 1], prev_t, tid);
}

// ---------------------------------------------------------------------------
extern "C" void kernel_launch(void* const* d_in, const int* in_sizes, int n_in,
                              void* d_out, int out_size) {
    const float* x   = (const float*)d_in[0];   // (32, 1e6) fp32
    const float* w   = (const float*)d_in[1];   // (5e5, 3)  fp32
    const int*   idx = (const int*)  d_in[2];   // (5e5, 3)  int32
    float*       out = (float*)d_out;           // (32, 5e5) fp32

    transpose_kernel<<<(N_IN + 127) / 128, 256>>>(x);
    gather_kernel<<<GATHER_BLOCKS, 256>>>(w, idx, out);
}